// round 7
// baseline (speedup 1.0000x reference)
#include <cuda_runtime.h>
#include <cuda_fp16.h>
#include <cstdint>

#define NPOS 48             // positions per block; 4032 = 84*48
#define TPB  84
#define NTILES 6            // NPOS/8
#define SMEM_TOTAL (16 * NTILES * 64 * 4)   // 24576 B: fp16 B-fragment act buffer

// Fragment-major FP16 weights: chunk[(l*16+kt)*16+mt][lane][4 words(b32)] = 512B
__device__ __align__(1024) uint32_t g_Wh[3 * 32768];

// byte offset of logical act[k][p] inside the fp16 B-fragment smem buffer
__device__ __forceinline__ uint32_t faddr16(int k, int p) {
    return (((((uint32_t)(k >> 4) * NTILES + (p >> 3)) * 64
            + ((p & 7) * 4 + ((k >> 1) & 3)) * 2 + ((k >> 3) & 1)) << 2)
            + ((k & 1) << 1));
}

__global__ void convert_w_kernel(const float* __restrict__ W1,
                                 const float* __restrict__ W2,
                                 const float* __restrict__ W3) {
    int i = blockIdx.x * blockDim.x + threadIdx.x;   // 98304 threads, 1 b32 word each
    int reg = i & 3, lane = (i >> 2) & 31, mt = (i >> 7) & 15, kt = (i >> 11) & 15, l = i >> 15;
    int g = lane >> 2, t = lane & 3;
    int row = mt * 16 + g + (reg & 1) * 8;            // output channel o
    int col = kt * 16 + 2 * t + (reg >> 1) * 8;       // input channel c
    const float* W = (l == 0) ? W1 : ((l == 1) ? W2 : W3);
    __half lo = __float2half_rn(W[row * 256 + col]);
    __half hi = __float2half_rn(W[row * 256 + col + 1]);
    g_Wh[i] = (uint32_t)__half_as_ushort(lo) | ((uint32_t)__half_as_ushort(hi) << 16);
}

__device__ __forceinline__ void mma_f16(float* d, const uint32_t* a, const uint32_t* b) {
    asm volatile(
        "mma.sync.aligned.m16n8k16.row.col.f32.f16.f16.f32 "
        "{%0,%1,%2,%3}, {%4,%5,%6,%7}, {%8,%9}, {%0,%1,%2,%3};"
        : "+f"(d[0]), "+f"(d[1]), "+f"(d[2]), "+f"(d[3])
        : "r"(a[0]), "r"(a[1]), "r"(a[2]), "r"(a[3]), "r"(b[0]), "r"(b[1]));
}

// 256 threads = 8 warps (4 m x 2 n); warp tile 64 outputs x 24 positions.
// 3 CTAs / SM (reg-capped at 85 by launch bounds).
__global__ __launch_bounds__(256, 3) void fused_kernel(
    const float* __restrict__ x,      // (32, 64, 64)
    const float* __restrict__ xc,     // (32, 128, 63, 64)
    const float* __restrict__ b1, const float* __restrict__ b2,
    const float* __restrict__ b3,
    float* __restrict__ out)          // (32, 256, 4032)
{
    extern __shared__ uint32_t actU[];
    char* const sc = (char*)actU;
    const int tid = threadIdx.x, lane = tid & 31, wid = tid >> 5;
    const int g = lane >> 2, t = lane & 3;
    const int wm = wid >> 1, wn = wid & 1;
    const int b = blockIdx.x / TPB, q0 = (blockIdx.x % TPB) * NPOS;

    // build 256ch x 48pos input tile directly as fp16 B-fragments
    for (int idx = tid; idx < 256 * NPOS; idx += 256) {
        int k = idx / NPOS, j = idx - k * NPOS;
        int q = q0 + j, h = q >> 6, w = q & 63;
        float v;
        if (k < 128)      v = xc[(size_t)(b * 128 + k) * 4032 + q];
        else if (k < 192) v = x[(b * 64 + (k - 128)) * 64 + w];
        else              v = x[(b * 64 + (k - 192)) * 64 + ((w - h - 1) & 63)];
        *(__half*)(sc + faddr16(k, j)) = __float2half_rn(v);
    }
    __syncthreads();

    const float* biases[3] = {b1, b2, b3};

    for (int l = 0; l < 3; l++) {
        float acc[4][3][4];
        #pragma unroll
        for (int mt = 0; mt < 4; mt++)
            #pragma unroll
            for (int nt = 0; nt < 3; nt++)
                #pragma unroll
                for (int r = 0; r < 4; r++) acc[mt][nt][r] = 0.f;

        const uint4* Ab = (const uint4*)g_Wh + (size_t)l * 8192 + lane;
        const uint2* Bb = (const uint2*)actU + lane;

        #pragma unroll 1
        for (int kt = 0; kt < 16; kt++) {
            uint32_t Br[3][2];
            #pragma unroll
            for (int nt = 0; nt < 3; nt++) {
                uint2 bv = Bb[(kt * NTILES + wn * 3 + nt) * 32];
                Br[nt][0] = bv.x; Br[nt][1] = bv.y;
            }
            uint32_t Ar[4][4];
            #pragma unroll
            for (int mt = 0; mt < 4; mt++) {
                uint4 av = Ab[(kt * 16 + wm * 4 + mt) * 32];
                Ar[mt][0] = av.x; Ar[mt][1] = av.y; Ar[mt][2] = av.z; Ar[mt][3] = av.w;
            }
            #pragma unroll
            for (int mt = 0; mt < 4; mt++)
                #pragma unroll
                for (int nt = 0; nt < 3; nt++)
                    mma_f16(acc[mt][nt], Ar[mt], Br[nt]);
        }

        __syncthreads();   // everyone done reading actU; safe to overwrite in place

        const float* bl = biases[l];
        if (l < 2) {
            #pragma unroll
            for (int mt = 0; mt < 4; mt++) {
                const int R0 = wm * 64 + mt * 16 + g;
                const float bb0 = bl[R0], bb8 = bl[R0 + 8];
                #pragma unroll
                for (int nt = 0; nt < 3; nt++) {
                    const int C0 = wn * 24 + nt * 8 + 2 * t;
                    *(__half*)(sc + faddr16(R0, C0)) =
                        __float2half_rn(fmaxf(acc[mt][nt][0] + bb0, 0.f));
                    *(__half*)(sc + faddr16(R0, C0 + 1)) =
                        __float2half_rn(fmaxf(acc[mt][nt][1] + bb0, 0.f));
                    *(__half*)(sc + faddr16(R0 + 8, C0)) =
                        __float2half_rn(fmaxf(acc[mt][nt][2] + bb8, 0.f));
                    *(__half*)(sc + faddr16(R0 + 8, C0 + 1)) =
                        __float2half_rn(fmaxf(acc[mt][nt][3] + bb8, 0.f));
                }
            }
            __syncthreads();
        } else {
            #pragma unroll
            for (int mt = 0; mt < 4; mt++) {
                const int R0 = wm * 64 + mt * 16 + g;
                const float bb0 = bl[R0], bb8 = bl[R0 + 8];
                float* p0 = out + ((size_t)(b * 256 + R0)) * 4032 + q0;
                float* p8 = p0 + (size_t)8 * 4032;
                #pragma unroll
                for (int nt = 0; nt < 3; nt++) {
                    const int C0 = wn * 24 + nt * 8 + 2 * t;
                    *(float2*)(p0 + C0) = make_float2(fmaxf(acc[mt][nt][0] + bb0, 0.f),
                                                      fmaxf(acc[mt][nt][1] + bb0, 0.f));
                    *(float2*)(p8 + C0) = make_float2(fmaxf(acc[mt][nt][2] + bb8, 0.f),
                                                      fmaxf(acc[mt][nt][3] + bb8, 0.f));
                }
            }
        }
    }
}

extern "C" void kernel_launch(void* const* d_in, const int* in_sizes, int n_in,
                              void* d_out, int out_size) {
    const float* x = nullptr; const float* xc = nullptr;
    const float* Ws[3] = {nullptr, nullptr, nullptr};
    const float* Bs[3] = {nullptr, nullptr, nullptr};
    int wi = 0, bi = 0;
    for (int i = 0; i < n_in; i++) {
        int sz = in_sizes[i];
        if (sz == 32 * 64 * 64)              x = (const float*)d_in[i];
        else if (sz == 32 * 128 * 63 * 64)   xc = (const float*)d_in[i];
        else if (sz == 256 * 256 && wi < 3)  Ws[wi++] = (const float*)d_in[i];
        else if (sz == 256 && bi < 3)        Bs[bi++] = (const float*)d_in[i];
    }
    convert_w_kernel<<<192, 512>>>(Ws[0], Ws[1], Ws[2]);
    cudaFuncSetAttribute(fused_kernel,
                         cudaFuncAttributeMaxDynamicSharedMemorySize, SMEM_TOTAL);
    fused_kernel<<<32 * TPB, 256, SMEM_TOTAL>>>(x, xc, Bs[0], Bs[1], Bs[2], (float*)d_out);
}

// round 8
// speedup vs baseline: 1.0123x; 1.0123x over previous
#include <cuda_runtime.h>
#include <cuda_fp16.h>
#include <cstdint>

#define NPOS 48             // positions per block; 4032 = 84*48
#define TPB  84
#define NTILES 6            // NPOS/8
#define SM_STAGE 24576      // act buffer is [0, 24576)
#define SMEM_TOTAL (24576 + 8 * 4096)   // + 8 warps x 2 bufs x 2KB W staging = 57344

// Fragment-major FP16 weights: chunk[(l*16+kt)*16+mt][lane][4 words(b32)] = 512B
__device__ __align__(1024) uint32_t g_Wh[3 * 32768];

// byte offset of logical act[k][p] inside the fp16 B-fragment smem buffer
__device__ __forceinline__ uint32_t faddr16(int k, int p) {
    return (((((uint32_t)(k >> 4) * NTILES + (p >> 3)) * 64
            + ((p & 7) * 4 + ((k >> 1) & 3)) * 2 + ((k >> 3) & 1)) << 2)
            + ((k & 1) << 1));
}

__global__ void convert_w_kernel(const float* __restrict__ W1,
                                 const float* __restrict__ W2,
                                 const float* __restrict__ W3) {
    int i = blockIdx.x * blockDim.x + threadIdx.x;   // 98304 threads, 1 b32 word each
    int reg = i & 3, lane = (i >> 2) & 31, mt = (i >> 7) & 15, kt = (i >> 11) & 15, l = i >> 15;
    int g = lane >> 2, t = lane & 3;
    int row = mt * 16 + g + (reg & 1) * 8;            // output channel o
    int col = kt * 16 + 2 * t + (reg >> 1) * 8;       // input channel c
    const float* W = (l == 0) ? W1 : ((l == 1) ? W2 : W3);
    __half lo = __float2half_rn(W[row * 256 + col]);
    __half hi = __float2half_rn(W[row * 256 + col + 1]);
    g_Wh[i] = (uint32_t)__half_as_ushort(lo) | ((uint32_t)__half_as_ushort(hi) << 16);
}

__device__ __forceinline__ void mma_f16(float* d, const uint32_t* a, const uint32_t* b) {
    asm volatile(
        "mma.sync.aligned.m16n8k16.row.col.f32.f16.f16.f32 "
        "{%0,%1,%2,%3}, {%4,%5,%6,%7}, {%8,%9}, {%0,%1,%2,%3};"
        : "+f"(d[0]), "+f"(d[1]), "+f"(d[2]), "+f"(d[3])
        : "r"(a[0]), "r"(a[1]), "r"(a[2]), "r"(a[3]), "r"(b[0]), "r"(b[1]));
}

#define CP16(d, s)  asm volatile("cp.async.ca.shared.global [%0], [%1], 16;" :: "r"(d), "l"(s) : "memory")
#define CPCOMMIT()  asm volatile("cp.async.commit_group;" ::: "memory")
#define CPWAIT1()   asm volatile("cp.async.wait_group 1;" ::: "memory")

// 256 threads = 8 warps (4 m x 2 n); warp tile 64 outputs x 24 positions.
// 3 CTAs / SM; per-warp double-buffered cp.async W staging.
__global__ __launch_bounds__(256, 3) void fused_kernel(
    const float* __restrict__ x,      // (32, 64, 64)
    const float* __restrict__ xc,     // (32, 128, 63, 64)
    const float* __restrict__ b1, const float* __restrict__ b2,
    const float* __restrict__ b3,
    float* __restrict__ out)          // (32, 256, 4032)
{
    extern __shared__ uint32_t actU[];
    char* const sc = (char*)actU;
    const int tid = threadIdx.x, lane = tid & 31, wid = tid >> 5;
    const int g = lane >> 2, t = lane & 3;
    const int wm = wid >> 1, wn = wid & 1;
    const int b = blockIdx.x / TPB, q0 = (blockIdx.x % TPB) * NPOS;

    // build 256ch x 48pos input tile directly as fp16 B-fragments
    for (int idx = tid; idx < 256 * NPOS; idx += 256) {
        int k = idx / NPOS, j = idx - k * NPOS;
        int q = q0 + j, h = q >> 6, w = q & 63;
        float v;
        if (k < 128)      v = xc[(size_t)(b * 128 + k) * 4032 + q];
        else if (k < 192) v = x[(b * 64 + (k - 128)) * 64 + w];
        else              v = x[(b * 64 + (k - 192)) * 64 + ((w - h - 1) & 63)];
        *(__half*)(sc + faddr16(k, j)) = __float2half_rn(v);
    }
    __syncthreads();

    // per-warp W staging region: two 2KB buffers
    char* const wstage = sc + SM_STAGE + wid * 4096;
    const uint32_t wstage_s =
        (uint32_t)__cvta_generic_to_shared(wstage) + (uint32_t)lane * 16u;

    const float* biases[3] = {b1, b2, b3};

    for (int l = 0; l < 3; l++) {
        float acc[4][3][4];
        #pragma unroll
        for (int mt = 0; mt < 4; mt++)
            #pragma unroll
            for (int nt = 0; nt < 3; nt++)
                #pragma unroll
                for (int r = 0; r < 4; r++) acc[mt][nt][r] = 0.f;

        const uint4* Wl = (const uint4*)g_Wh + (size_t)l * 8192;
        const uint2* Bb = (const uint2*)actU + lane;

        // prologue: stage k-step 0 into buffer 0
        {
            const uint4* s0 = Wl + (wm * 4) * 32 + lane;
            #pragma unroll
            for (int mt = 0; mt < 4; mt++) CP16(wstage_s + mt * 512, s0 + mt * 32);
            CPCOMMIT();
        }

        #pragma unroll 2
        for (int kt = 0; kt < 16; kt++) {
            if (kt < 15) {   // prefetch k-step kt+1 into the other buffer
                const uint4* s = Wl + ((kt + 1) * 16 + wm * 4) * 32 + lane;
                const uint32_t d = wstage_s + (uint32_t)(((kt + 1) & 1) * 2048);
                #pragma unroll
                for (int mt = 0; mt < 4; mt++) CP16(d + mt * 512, s + mt * 32);
            }
            CPCOMMIT();
            CPWAIT1();       // k-step kt's group is now complete

            uint32_t Br[3][2];
            #pragma unroll
            for (int nt = 0; nt < 3; nt++) {
                uint2 bv = Bb[(kt * NTILES + wn * 3 + nt) * 32];
                Br[nt][0] = bv.x; Br[nt][1] = bv.y;
            }
            const char* abuf = wstage + (kt & 1) * 2048 + lane * 16;
            #pragma unroll
            for (int mt = 0; mt < 4; mt++) {
                uint4 av = *(const uint4*)(abuf + mt * 512);
                uint32_t Ar[4] = {av.x, av.y, av.z, av.w};
                #pragma unroll
                for (int nt = 0; nt < 3; nt++)
                    mma_f16(acc[mt][nt], Ar, Br[nt]);
            }
        }

        __syncthreads();   // everyone done reading actU; safe to overwrite in place

        const float* bl = biases[l];
        if (l < 2) {
            #pragma unroll
            for (int mt = 0; mt < 4; mt++) {
                const int R0 = wm * 64 + mt * 16 + g;
                const float bb0 = bl[R0], bb8 = bl[R0 + 8];
                #pragma unroll
                for (int nt = 0; nt < 3; nt++) {
                    const int C0 = wn * 24 + nt * 8 + 2 * t;
                    *(__half*)(sc + faddr16(R0, C0)) =
                        __float2half_rn(fmaxf(acc[mt][nt][0] + bb0, 0.f));
                    *(__half*)(sc + faddr16(R0, C0 + 1)) =
                        __float2half_rn(fmaxf(acc[mt][nt][1] + bb0, 0.f));
                    *(__half*)(sc + faddr16(R0 + 8, C0)) =
                        __float2half_rn(fmaxf(acc[mt][nt][2] + bb8, 0.f));
                    *(__half*)(sc + faddr16(R0 + 8, C0 + 1)) =
                        __float2half_rn(fmaxf(acc[mt][nt][3] + bb8, 0.f));
                }
            }
            __syncthreads();
        } else {
            #pragma unroll
            for (int mt = 0; mt < 4; mt++) {
                const int R0 = wm * 64 + mt * 16 + g;
                const float bb0 = bl[R0], bb8 = bl[R0 + 8];
                float* p0 = out + ((size_t)(b * 256 + R0)) * 4032 + q0;
                float* p8 = p0 + (size_t)8 * 4032;
                #pragma unroll
                for (int nt = 0; nt < 3; nt++) {
                    const int C0 = wn * 24 + nt * 8 + 2 * t;
                    *(float2*)(p0 + C0) = make_float2(fmaxf(acc[mt][nt][0] + bb0, 0.f),
                                                      fmaxf(acc[mt][nt][1] + bb0, 0.f));
                    *(float2*)(p8 + C0) = make_float2(fmaxf(acc[mt][nt][2] + bb8, 0.f),
                                                      fmaxf(acc[mt][nt][3] + bb8, 0.f));
                }
            }
        }
    }
}

extern "C" void kernel_launch(void* const* d_in, const int* in_sizes, int n_in,
                              void* d_out, int out_size) {
    const float* x = nullptr; const float* xc = nullptr;
    const float* Ws[3] = {nullptr, nullptr, nullptr};
    const float* Bs[3] = {nullptr, nullptr, nullptr};
    int wi = 0, bi = 0;
    for (int i = 0; i < n_in; i++) {
        int sz = in_sizes[i];
        if (sz == 32 * 64 * 64)              x = (const float*)d_in[i];
        else if (sz == 32 * 128 * 63 * 64)   xc = (const float*)d_in[i];
        else if (sz == 256 * 256 && wi < 3)  Ws[wi++] = (const float*)d_in[i];
        else if (sz == 256 && bi < 3)        Bs[bi++] = (const float*)d_in[i];
    }
    convert_w_kernel<<<192, 512>>>(Ws[0], Ws[1], Ws[2]);
    cudaFuncSetAttribute(fused_kernel,
                         cudaFuncAttributeMaxDynamicSharedMemorySize, SMEM_TOTAL);
    fused_kernel<<<32 * TPB, 256, SMEM_TOTAL>>>(x, xc, Bs[0], Bs[1], Bs[2], (float*)d_out);
}